// round 8
// baseline (speedup 1.0000x reference)
#include <cuda_runtime.h>
#include <cuda_fp16.h>
#include <cstdint>
#include <cstddef>

#define N_NODES   100000
#define N_EDGES   1600000
#define IN_F      64
#define OUT_F     64
#define KK        4
#define CAP       64
#define OVF_CAP   8192

// Static scratch.
__device__ __half2 g_feat16[(size_t)N_NODES * 32];   // feat fp16 [N][64]
__device__ int     g_deg[N_NODES];
__device__ uint4   g_rec[(size_t)N_NODES * CAP];     // 16B: {g01,g23 fp16 | src | pad}
__device__ __half2 g_agg[(size_t)N_NODES * 128];     // agg[N][256] fp16
__device__ __half  g_W16[64 * 256];                  // W fp16, [o][ch*64+i]
__device__ int     g_ovf_cnt;
__device__ uint4   g_ovf[OVF_CAP * 2];

// FMA-pipe exp(x) for x <= 0 (no MUFU). rel err ~1e-6.
__device__ __forceinline__ float fast_exp(float x)
{
    float t = x * 1.44269504f;
    float n = rintf(t);
    float u = (t - n) * 0.69314718056f;   // |u| <= 0.347
    float p = 1.f + u * (1.f + u * (0.5f + u * (0.166666667f
                + u * (0.0416666667f + u * 0.00833333333f))));
    int ni = (int)n;
    ni = ni < -126 ? -126 : ni;
    return p * __int_as_float((ni + 127) << 23);
}

// ---------------------------------------------------------------------------
// k0: feat -> fp16; W -> fp16 (B layout); zero counters.
// ---------------------------------------------------------------------------
__global__ __launch_bounds__(256) void prep_kernel(const float* __restrict__ feat,
                                                   const float* __restrict__ W)
{
    const int gid    = blockIdx.x * 256 + threadIdx.x;
    const int stride = gridDim.x * 256;
    const float2* f2 = reinterpret_cast<const float2*>(feat);
    for (int i = gid; i < N_NODES * 32; i += stride)
        g_feat16[i] = __float22half2_rn(f2[i]);
    if (gid < N_NODES) g_deg[gid] = 0;
    if (gid == 0)      g_ovf_cnt  = 0;
    // W fp16: g_W16[o][c] = W[(c>>6)*64 + o][c & 63]
    if (gid < 8192) {
        const int o  = gid >> 7;          // 0..63
        const int c  = (gid & 127) * 2;   // even column
        const int ch = c >> 6;
        const int i  = c & 63;
        const float* wr = W + (size_t)(ch * 64 + o) * IN_F + i;
        *reinterpret_cast<__half2*>(g_W16 + (size_t)o * 256 + c) =
            __floats2half2_rn(wr[0], wr[1]);
    }
}

// ---------------------------------------------------------------------------
// k1: Gaussian weights (FMA fast-exp) + bin 16B record into dst slot list.
// ---------------------------------------------------------------------------
__global__ __launch_bounds__(256) void bin_kernel(
    const float* __restrict__ pseudo,
    const int*   __restrict__ src,
    const int*   __restrict__ dst,
    const float* __restrict__ mu,
    const float* __restrict__ inv_sigma)
{
    const int e = blockIdx.x * 256 + threadIdx.x;
    const float p0 = __ldg(pseudo + 3 * (size_t)e + 0);
    const float p1 = __ldg(pseudo + 3 * (size_t)e + 1);
    const float p2 = __ldg(pseudo + 3 * (size_t)e + 2);
    const int s = src[e];
    const int d = dst[e];

    float g[KK];
    #pragma unroll
    for (int k = 0; k < KK; k++) {
        float m0 = __ldg(mu + 3 * k + 0), m1 = __ldg(mu + 3 * k + 1), m2 = __ldg(mu + 3 * k + 2);
        float s0 = __ldg(inv_sigma + 3 * k + 0), s1 = __ldg(inv_sigma + 3 * k + 1), s2 = __ldg(inv_sigma + 3 * k + 2);
        float dx = p0 - m0, dy = p1 - m1, dz = p2 - m2;
        float w = dx * dx * (s0 * s0) + dy * dy * (s1 * s1) + dz * dz * (s2 * s2);
        g[k] = fast_exp(-0.5f * w);
    }

    const int pos = atomicAdd(&g_deg[d], 1);
    if (pos < CAP) {
        __half2 h01 = __floats2half2_rn(g[0], g[1]);
        __half2 h23 = __floats2half2_rn(g[2], g[3]);
        uint4 rec;
        rec.x = *reinterpret_cast<const uint32_t*>(&h01);
        rec.y = *reinterpret_cast<const uint32_t*>(&h23);
        rec.z = (unsigned)s;
        rec.w = 0u;
        g_rec[(size_t)d * CAP + pos] = rec;
    } else {
        const int oi = atomicAdd(&g_ovf_cnt, 1);
        if (oi < OVF_CAP) {
            g_ovf[oi * 2] = make_uint4(__float_as_uint(g[0]), __float_as_uint(g[1]),
                                       __float_as_uint(g[2]), __float_as_uint(g[3]));
            g_ovf[oi * 2 + 1] = make_uint4((unsigned)s, (unsigned)d, 0u, 0u);
        }
    }
}

// ---------------------------------------------------------------------------
// k2: aggregate. Warp-per-node, records staged to smem, one warp-wide 128B
// feat16 gather per edge, fp32 accum, no atomics. Grid = 12500 exact.
// ---------------------------------------------------------------------------
__global__ __launch_bounds__(256) void agg_kernel()
{
    __shared__ uint4 srec[8][CAP];   // 8 KB

    const int w    = threadIdx.x >> 5;
    const int lane = threadIdx.x & 31;
    const int v    = blockIdx.x * 8 + w;

    int d = g_deg[v];
    if (d > CAP) d = CAP;

    const size_t base = (size_t)v * CAP;
    if (lane < d)      srec[w][lane]      = g_rec[base + lane];
    if (lane + 32 < d) srec[w][lane + 32] = g_rec[base + lane + 32];
    __syncwarp();

    float2 a0 = make_float2(0.f, 0.f), a1 = make_float2(0.f, 0.f);
    float2 a2 = make_float2(0.f, 0.f), a3 = make_float2(0.f, 0.f);

    #pragma unroll 4
    for (int j = 0; j < d; j++) {
        const uint4 r = srec[w][j];
        const float2 g01 = __half22float2(*reinterpret_cast<const __half2*>(&r.x));
        const float2 g23 = __half22float2(*reinterpret_cast<const __half2*>(&r.y));
        const float2 f = __half22float2(g_feat16[(size_t)r.z * 32 + lane]);
        a0.x += g01.x * f.x; a0.y += g01.x * f.y;
        a1.x += g01.y * f.x; a1.y += g01.y * f.y;
        a2.x += g23.x * f.x; a2.y += g23.x * f.y;
        a3.x += g23.y * f.x; a3.y += g23.y * f.y;
    }

    __half2* ar = g_agg + (size_t)v * 128;
    ar[0 * 32 + lane] = __float22half2_rn(a0);
    ar[1 * 32 + lane] = __float22half2_rn(a1);
    ar[2 * 32 + lane] = __float22half2_rn(a2);
    ar[3 * 32 + lane] = __float22half2_rn(a3);
}

// ---------------------------------------------------------------------------
// k3: out = agg @ W' + feat + bias. One-shot staging (sA/sB [64][264] fp16),
// one __syncthreads, then 16 uninterrupted ldmatrix+HMMA steps.
// Dynamic smem 67,584 B -> 3 blocks/SM.
// ---------------------------------------------------------------------------
#define GEMM_SMEM  (2 * 64 * 264 * 2)   // 67584

__global__ __launch_bounds__(256) void gemm_kernel(
    const float* __restrict__ feat,
    const float* __restrict__ bias,
    float* __restrict__ out)
{
    extern __shared__ char smem[];
    __half (*sA)[264] = reinterpret_cast<__half(*)[264]>(smem);
    __half (*sB)[264] = reinterpret_cast<__half(*)[264]>(smem + 64 * 264 * 2);

    const int tid  = threadIdx.x;
    const int row0 = blockIdx.x * 64;
    const int lane = tid & 31;
    const int w    = tid >> 5;

    // ---- stage A (agg rows) and B (g_W16), conflict-free (r, sgm) map ----
    {
        const int r   = tid >> 2;        // 0..63
        const int sgm = tid & 3;         // 16-half slice within each 64-half chunk
        int gr = row0 + r;
        if (gr >= N_NODES) gr = N_NODES - 1;
        const uint4* ap = reinterpret_cast<const uint4*>(g_agg + (size_t)gr * 128);
        const uint4* bp = reinterpret_cast<const uint4*>(g_W16 + (size_t)r * 256);
        #pragma unroll
        for (int ch = 0; ch < 4; ch++) {
            *reinterpret_cast<uint4*>(&sA[r][ch * 64 + sgm * 16])     = ap[ch * 8 + sgm * 2];
            *reinterpret_cast<uint4*>(&sA[r][ch * 64 + sgm * 16 + 8]) = ap[ch * 8 + sgm * 2 + 1];
            *reinterpret_cast<uint4*>(&sB[r][ch * 64 + sgm * 16])     = bp[ch * 8 + sgm * 2];
            *reinterpret_cast<uint4*>(&sB[r][ch * 64 + sgm * 16 + 8]) = bp[ch * 8 + sgm * 2 + 1];
        }
    }
    __syncthreads();

    // ---- 64x64 = sA[64,256] @ sB^T via ldmatrix + HMMA ----
    const int mb = (w & 3) * 16;
    const int nb = (w >> 2) * 32;
    const int t8 = lane >> 3;
    const int r8 = lane & 7;

    const uint32_t sA_u = (uint32_t)__cvta_generic_to_shared(&sA[0][0]);
    const uint32_t sB_u = (uint32_t)__cvta_generic_to_shared(&sB[0][0]);
    const uint32_t aBase   = sA_u + (uint32_t)(((mb + ((t8 & 1) << 3) + r8) * 264 + ((t8 >> 1) << 3)) << 1);
    const uint32_t bBase01 = sB_u + (uint32_t)(((nb + ((t8 >> 1) << 3) + r8) * 264 + ((t8 & 1) << 3)) << 1);
    const uint32_t bBase23 = bBase01 + (16 * 264 * 2);

    float acc[4][4];
    #pragma unroll
    for (int nt = 0; nt < 4; nt++)
        acc[nt][0] = acc[nt][1] = acc[nt][2] = acc[nt][3] = 0.f;

    #pragma unroll
    for (int ks = 0; ks < 16; ks++) {
        const uint32_t koff = ks * 32;   // 16 halves = 32 B
        uint32_t a0, a1, a2, a3, b0[4], b1[4];
        asm volatile("ldmatrix.sync.aligned.m8n8.x4.shared.b16 {%0,%1,%2,%3}, [%4];"
            : "=r"(a0), "=r"(a1), "=r"(a2), "=r"(a3) : "r"(aBase + koff));
        asm volatile("ldmatrix.sync.aligned.m8n8.x4.shared.b16 {%0,%1,%2,%3}, [%4];"
            : "=r"(b0[0]), "=r"(b0[1]), "=r"(b0[2]), "=r"(b0[3]) : "r"(bBase01 + koff));
        asm volatile("ldmatrix.sync.aligned.m8n8.x4.shared.b16 {%0,%1,%2,%3}, [%4];"
            : "=r"(b1[0]), "=r"(b1[1]), "=r"(b1[2]), "=r"(b1[3]) : "r"(bBase23 + koff));

        asm volatile("mma.sync.aligned.m16n8k16.row.col.f32.f16.f16.f32 "
            "{%0,%1,%2,%3}, {%4,%5,%6,%7}, {%8,%9}, {%0,%1,%2,%3};"
            : "+f"(acc[0][0]), "+f"(acc[0][1]), "+f"(acc[0][2]), "+f"(acc[0][3])
            : "r"(a0), "r"(a1), "r"(a2), "r"(a3), "r"(b0[0]), "r"(b0[1]));
        asm volatile("mma.sync.aligned.m16n8k16.row.col.f32.f16.f16.f32 "
            "{%0,%1,%2,%3}, {%4,%5,%6,%7}, {%8,%9}, {%0,%1,%2,%3};"
            : "+f"(acc[1][0]), "+f"(acc[1][1]), "+f"(acc[1][2]), "+f"(acc[1][3])
            : "r"(a0), "r"(a1), "r"(a2), "r"(a3), "r"(b0[2]), "r"(b0[3]));
        asm volatile("mma.sync.aligned.m16n8k16.row.col.f32.f16.f16.f32 "
            "{%0,%1,%2,%3}, {%4,%5,%6,%7}, {%8,%9}, {%0,%1,%2,%3};"
            : "+f"(acc[2][0]), "+f"(acc[2][1]), "+f"(acc[2][2]), "+f"(acc[2][3])
            : "r"(a0), "r"(a1), "r"(a2), "r"(a3), "r"(b1[0]), "r"(b1[1]));
        asm volatile("mma.sync.aligned.m16n8k16.row.col.f32.f16.f16.f32 "
            "{%0,%1,%2,%3}, {%4,%5,%6,%7}, {%8,%9}, {%0,%1,%2,%3};"
            : "+f"(acc[3][0]), "+f"(acc[3][1]), "+f"(acc[3][2]), "+f"(acc[3][3])
            : "r"(a0), "r"(a1), "r"(a2), "r"(a3), "r"(b1[2]), "r"(b1[3]));
    }

    // ---- epilogue: out = acc + feat + bias ----
    const int g2  = lane >> 2;
    const int tig = lane & 3;
    const int r0 = row0 + mb + g2;
    const int r1 = r0 + 8;
    #pragma unroll
    for (int nt = 0; nt < 4; nt++) {
        const int col = nb + nt * 8 + tig * 2;
        const float2 b = *reinterpret_cast<const float2*>(bias + col);
        if (r0 < N_NODES) {
            const float2 f = *reinterpret_cast<const float2*>(feat + (size_t)r0 * IN_F + col);
            *reinterpret_cast<float2*>(out + (size_t)r0 * OUT_F + col) =
                make_float2(acc[nt][0] + f.x + b.x, acc[nt][1] + f.y + b.y);
        }
        if (r1 < N_NODES) {
            const float2 f = *reinterpret_cast<const float2*>(feat + (size_t)r1 * IN_F + col);
            *reinterpret_cast<float2*>(out + (size_t)r1 * OUT_F + col) =
                make_float2(acc[nt][2] + f.x + b.x, acc[nt][3] + f.y + b.y);
        }
    }
}

// ---------------------------------------------------------------------------
// k4: drain overflow (statistically never runs; cheap early-out).
// ---------------------------------------------------------------------------
__global__ __launch_bounds__(256) void ovf_kernel(const float* __restrict__ feat,
                                                  const float* __restrict__ W,
                                                  float* __restrict__ out)
{
    int cnt = g_ovf_cnt;
    if (cnt <= 0) return;
    if (cnt > OVF_CAP) cnt = OVF_CAP;
    const int o   = threadIdx.x & 63;
    const int row = (blockIdx.x * 256 + threadIdx.x) >> 6;
    const int stride = (gridDim.x * 256) >> 6;
    for (int i = row; i < cnt; i += stride) {
        const float4 gg = *reinterpret_cast<const float4*>(&g_ovf[i * 2]);
        const int s = (int)g_ovf[i * 2 + 1].x;
        const int d = (int)g_ovf[i * 2 + 1].y;
        const float gk[4] = {gg.x, gg.y, gg.z, gg.w};
        float val = 0.f;
        for (int k = 0; k < KK; k++) {
            float hk = 0.f;
            for (int ii = 0; ii < IN_F; ii++)
                hk += W[(size_t)(k * 64 + o) * IN_F + ii] * feat[(size_t)s * IN_F + ii];
            val += gk[k] * hk;
        }
        atomicAdd(out + (size_t)d * OUT_F + o, val);
    }
}

// ---------------------------------------------------------------------------
extern "C" void kernel_launch(void* const* d_in, const int* in_sizes, int n_in,
                              void* d_out, int out_size)
{
    const float* feat      = (const float*)d_in[0];
    const float* pseudo    = (const float*)d_in[1];
    const int*   src       = (const int*)d_in[2];
    const int*   dst       = (const int*)d_in[3];
    const float* W_fc      = (const float*)d_in[4];
    const float* mu        = (const float*)d_in[5];
    const float* inv_sigma = (const float*)d_in[6];
    const float* bias      = (const float*)d_in[7];
    float* out = (float*)d_out;

    cudaFuncSetAttribute(gemm_kernel,
                         cudaFuncAttributeMaxDynamicSharedMemorySize, GEMM_SMEM);

    prep_kernel<<<3125, 256>>>(feat, W_fc);
    bin_kernel<<<N_EDGES / 256, 256>>>(pseudo, src, dst, mu, inv_sigma);
    agg_kernel<<<N_NODES / 8, 256>>>();
    gemm_kernel<<<(N_NODES + 63) / 64, 256, GEMM_SMEM>>>(feat, bias, out);
    ovf_kernel<<<8, 256>>>(feat, W_fc, out);
}